// round 8
// baseline (speedup 1.0000x reference)
#include <cuda_runtime.h>
#include <mma.h>
#include <math.h>
#include <stdint.h>

using namespace nvcuda;

#define NBLK    128        // CTAs, 64 rows each
#define THREADS 512
#define F_IN    512
#define H_DIM   256
#define W_DIM   64

// pads with gcd(LD,32)=4 -> <=2-way bank conflicts
#define LDX 36             // X chunk   [64][32]
#define LDB 260            // W chunk   [32][256]
#define LDC 260            // act tiles [64][256]
#define LDQ 68             // Wq chunk  [32][64], also C3 [64][64]

// float offsets inside dynamic smem
#define O_X    0                    // 2 x 64*36  = 4608
#define O_B    4608                 // 2 x 32*260 = 16640
#define O_A1   21248                // 64*260     = 16640
#define O_A2   37888                // 64*260     = 16640
#define O_CON  54528                // b1(256) b2(256) bq(64) wh(64) red(16) flg(1)
#define SMEMF  55186
#define SMEM_BYTES (SMEMF * 4)      // 220744 B

static __device__ float g_part[NBLK];
static __device__ unsigned int g_cnt = 0;

__device__ __forceinline__ float f2tf(float f) {   // round-to-nearest tf32
    uint32_t r;
    asm("cvt.rna.tf32.f32 %0, %1;" : "=r"(r) : "f"(f));
    return __uint_as_float(r);
}

typedef wmma::fragment<wmma::matrix_a, 16, 16, 8, wmma::precision::tf32, wmma::row_major> FragA;
typedef wmma::fragment<wmma::matrix_b, 16, 16, 8, wmma::precision::tf32, wmma::row_major> FragB;
typedef wmma::fragment<wmma::accumulator, 16, 16, 8, float> FragC;

__global__ void __launch_bounds__(THREADS, 1)
fused_wmma(const float* __restrict__ X,
           const float* __restrict__ W1, const float* __restrict__ b1,
           const float* __restrict__ W2, const float* __restrict__ b2,
           const float* __restrict__ Wq, const float* __restrict__ bq,
           const float* __restrict__ Wh, const float* __restrict__ bh,
           float* __restrict__ out)
{
    extern __shared__ float sm[];
    float* sX  = sm + O_X;
    float* sB  = sm + O_B;
    float* sA1 = sm + O_A1;
    float* sA2 = sm + O_A2;
    float* b1s = sm + O_CON;
    float* b2s = b1s + 256;
    float* bqs = b2s + 256;
    float* whs = bqs + 64;
    float* red = whs + 64;
    float* flg = red + 16;

    const int t = threadIdx.x;
    const int w = t >> 5;         // 0..15
    const int row0 = blockIdx.x * 64;
    const int mi = w >> 2;        // 0..3 : M-tile (16 rows)
    const int ng = w & 3;         // 0..3 : N-group (4 j-tiles L1/L2; 1 j-tile L3)

    // ---- consts ----
    if (t < 256) { b1s[t] = b1[t]; b2s[t] = b2[t]; }
    else if (t < 320) { bqs[t - 256] = bq[t - 256]; whs[t - 256] = Wh[t - 256]; }

    // ---- fill helpers (512 threads) ----
    auto fillX = [&](int s, int buf) {   // X chunk 64x32 -> sX[buf]; 512 f4
        float* dst = sX + buf * 2304;
        const int r = t >> 3, c4 = t & 7;
        float4 v = *reinterpret_cast<const float4*>(X + (size_t)(row0 + r) * F_IN + s * 32 + c4 * 4);
        float4 o = make_float4(f2tf(v.x), f2tf(v.y), f2tf(v.z), f2tf(v.w));
        *reinterpret_cast<float4*>(dst + r * LDX + c4 * 4) = o;
    };
    auto fillW = [&](const float* __restrict__ W, int s, int buf) {  // 32x256; 2048 f4
        float* dst = sB + buf * 8320;
        #pragma unroll
        for (int kq = 0; kq < 4; ++kq) {
            const int idx = t + kq * 512;
            const int r = idx >> 6, c4 = idx & 63;
            float4 v = *reinterpret_cast<const float4*>(W + (size_t)(s * 32 + r) * H_DIM + c4 * 4);
            float4 o = make_float4(f2tf(v.x), f2tf(v.y), f2tf(v.z), f2tf(v.w));
            *reinterpret_cast<float4*>(dst + r * LDB + c4 * 4) = o;
        }
    };
    auto fillWq = [&](int s, int buf) {  // 32x64; 512 f4
        float* dst = sB + buf * 8320;
        const int r = t >> 4, c4 = t & 15;
        float4 v = *reinterpret_cast<const float4*>(Wq + (size_t)(s * 32 + r) * W_DIM + c4 * 4);
        float4 o = make_float4(f2tf(v.x), f2tf(v.y), f2tf(v.z), f2tf(v.w));
        *reinterpret_cast<float4*>(dst + r * LDQ + c4 * 4) = o;
    };

    // ================= Layer 1: C1 = X @ W1  (K=512) =================
    FragC acc[4];
    #pragma unroll
    for (int j = 0; j < 4; ++j) wmma::fill_fragment(acc[j], 0.0f);

    fillX(0, 0); fillW(W1, 0, 0);
    __syncthreads();
    for (int s = 0; s < 16; ++s) {
        const int cb = s & 1;
        if (s < 15) { fillX(s + 1, (s + 1) & 1); fillW(W1, s + 1, (s + 1) & 1); }
        const float* ax = sX + cb * 2304;
        const float* bx = sB + cb * 8320;
        #pragma unroll
        for (int kk = 0; kk < 32; kk += 8) {
            FragA a;
            wmma::load_matrix_sync(a, ax + mi * 16 * LDX + kk, LDX);
            #pragma unroll
            for (int j = 0; j < 4; ++j) {
                FragB b;
                wmma::load_matrix_sync(b, bx + kk * LDB + (ng * 4 + j) * 16, LDB);
                wmma::mma_sync(acc[j], a, b, acc[j]);
            }
        }
        __syncthreads();
    }
    #pragma unroll
    for (int j = 0; j < 4; ++j)
        wmma::store_matrix_sync(sA1 + mi * 16 * LDC + (ng * 4 + j) * 16, acc[j], LDC, wmma::mem_row_major);
    __syncthreads();
    #pragma unroll
    for (int i = 0; i < 32; ++i) {      // relu + b1, tf32-round in place
        const int idx = t + i * 512;
        const int r = idx >> 8, c = idx & 255;
        sA1[r * LDC + c] = f2tf(fmaxf(sA1[r * LDC + c] + b1s[c], 0.0f));
    }
    __syncthreads();

    // ================= Layer 2: C2 = act1 @ W2  (K=256) =================
    #pragma unroll
    for (int j = 0; j < 4; ++j) wmma::fill_fragment(acc[j], 0.0f);
    fillW(W2, 0, 0);
    __syncthreads();
    for (int s = 0; s < 8; ++s) {
        const int cb = s & 1;
        if (s < 7) fillW(W2, s + 1, (s + 1) & 1);
        const float* bx = sB + cb * 8320;
        #pragma unroll
        for (int kk = 0; kk < 32; kk += 8) {
            FragA a;
            wmma::load_matrix_sync(a, sA1 + mi * 16 * LDC + s * 32 + kk, LDC);
            #pragma unroll
            for (int j = 0; j < 4; ++j) {
                FragB b;
                wmma::load_matrix_sync(b, bx + kk * LDB + (ng * 4 + j) * 16, LDB);
                wmma::mma_sync(acc[j], a, b, acc[j]);
            }
        }
        __syncthreads();
    }
    #pragma unroll
    for (int j = 0; j < 4; ++j)
        wmma::store_matrix_sync(sA2 + mi * 16 * LDC + (ng * 4 + j) * 16, acc[j], LDC, wmma::mem_row_major);
    __syncthreads();
    #pragma unroll
    for (int i = 0; i < 32; ++i) {      // relu + b2
        const int idx = t + i * 512;
        const int r = idx >> 8, c = idx & 255;
        sA2[r * LDC + c] = f2tf(fmaxf(sA2[r * LDC + c] + b2s[c], 0.0f));
    }
    __syncthreads();

    // ================= Layer 3: C3 = act2 @ Wq  (K=256, N=64) =================
    FragC a3;
    wmma::fill_fragment(a3, 0.0f);
    fillWq(0, 0);
    __syncthreads();
    for (int s = 0; s < 8; ++s) {
        const int cb = s & 1;
        if (s < 7) fillWq(s + 1, (s + 1) & 1);
        const float* bx = sB + cb * 8320;
        #pragma unroll
        for (int kk = 0; kk < 32; kk += 8) {
            FragA a;
            wmma::load_matrix_sync(a, sA2 + mi * 16 * LDC + s * 32 + kk, LDC);
            FragB b;
            wmma::load_matrix_sync(b, bx + kk * LDQ + ng * 16, LDQ);
            wmma::mma_sync(a3, a, b, a3);
        }
        __syncthreads();
    }
    wmma::store_matrix_sync(sA1 + mi * 16 * LDQ + ng * 16, a3, LDQ, wmma::mem_row_major);
    __syncthreads();

    // ---- Epilogue: sum_{r,c} tanh(C3 + bq[c]) * Wh[c]  -> per-CTA scalar ----
    float p = 0.0f;
    {
        const int r  = t & 63;
        const int c0 = (t >> 6) * 8;     // 8 groups x 8 cols
        #pragma unroll
        for (int c = 0; c < 8; ++c)
            p += tanhf(sA1[r * LDQ + c0 + c] + bqs[c0 + c]) * whs[c0 + c];
    }
    #pragma unroll
    for (int off = 16; off > 0; off >>= 1)
        p += __shfl_down_sync(0xffffffffu, p, off);
    if ((t & 31) == 0) red[w] = p;
    __syncthreads();
    if (t == 0) {
        float s = 0.0f;
        #pragma unroll
        for (int i = 0; i < 16; ++i) s += red[i];
        g_part[blockIdx.x] = s;
        __threadfence();
        unsigned int v = atomicAdd(&g_cnt, 1u);
        flg[0] = (v == NBLK - 1) ? 1.0f : 0.0f;
    }
    __syncthreads();

    // ---- Last CTA: final reduction (fixed order -> deterministic) ----
    if (flg[0] != 0.0f) {
        __threadfence();
        float v = 0.0f;
        if (t < 128) v = g_part[t];
        #pragma unroll
        for (int off = 16; off > 0; off >>= 1)
            v += __shfl_down_sync(0xffffffffu, v, off);
        if ((t & 31) == 0 && w < 4) red[w] = v;
        __syncthreads();
        if (t == 0) {
            out[0] = (red[0] + red[1]) + (red[2] + red[3]) + bh[0];
            g_cnt = 0;                    // reset for next graph replay
        }
    }
}

extern "C" void kernel_launch(void* const* d_in, const int* in_sizes, int n_in,
                              void* d_out, int out_size)
{
    const float* X  = (const float*)d_in[0];
    const float* W1 = (const float*)d_in[1];
    const float* b1 = (const float*)d_in[2];
    const float* W2 = (const float*)d_in[3];
    const float* b2 = (const float*)d_in[4];
    const float* Wq = (const float*)d_in[5];
    const float* bq = (const float*)d_in[6];
    const float* Wh = (const float*)d_in[7];
    const float* bh = (const float*)d_in[8];

    cudaFuncSetAttribute(fused_wmma, cudaFuncAttributeMaxDynamicSharedMemorySize, SMEM_BYTES);
    fused_wmma<<<NBLK, THREADS, SMEM_BYTES>>>(X, W1, b1, W2, b2, Wq, bq, Wh, bh, (float*)d_out);
}

// round 9
// speedup vs baseline: 1.0575x; 1.0575x over previous
#include <cuda_runtime.h>
#include <mma.h>
#include <math.h>
#include <stdint.h>

using namespace nvcuda;

#define NBLK    256        // CTAs, 32 rows each
#define THREADS 256
#define F_IN    512
#define H_DIM   256
#define W_DIM   64

#define LDX 36             // X chunk  [32][32]
#define LDB 260            // W chunk  [32][256]; also act tile [32][256]
#define LDQ 68             // Wq chunk [32][64];  also C3 [32][64]

// float offsets inside dynamic smem
#define O_X    0                    // 2 x 32*36  = 2304
#define O_B    2304                 // 2 x 32*260 = 16640
#define O_A    18944                // 32*260     = 8320 (act, reused in place)
#define O_CON  27264                // b1(256) b2(256) bq(64) wh(64) red(8) flg(1)
#define SMEMF  27914
#define SMEM_BYTES (SMEMF * 4)      // 111656 B  -> 2 CTAs/SM

static __device__ float g_part[NBLK];
static __device__ unsigned int g_cnt = 0;

__device__ __forceinline__ float f2tf(float f) {   // round-to-nearest tf32
    uint32_t r;
    asm("cvt.rna.tf32.f32 %0, %1;" : "=r"(r) : "f"(f));
    return __uint_as_float(r);
}

typedef wmma::fragment<wmma::matrix_a, 16, 16, 8, wmma::precision::tf32, wmma::row_major> FragA;
typedef wmma::fragment<wmma::matrix_b, 16, 16, 8, wmma::precision::tf32, wmma::row_major> FragB;
typedef wmma::fragment<wmma::accumulator, 16, 16, 8, float> FragC;

__global__ void __launch_bounds__(THREADS, 2)
fused_wmma(const float* __restrict__ X,
           const float* __restrict__ W1, const float* __restrict__ b1,
           const float* __restrict__ W2, const float* __restrict__ b2,
           const float* __restrict__ Wq, const float* __restrict__ bq,
           const float* __restrict__ Wh, const float* __restrict__ bh,
           float* __restrict__ out)
{
    extern __shared__ float sm[];
    float* sX  = sm + O_X;
    float* sB  = sm + O_B;
    float* sA  = sm + O_A;
    float* b1s = sm + O_CON;
    float* b2s = b1s + 256;
    float* bqs = b2s + 256;
    float* whs = bqs + 64;
    float* red = whs + 64;
    float* flg = red + 8;

    const int t = threadIdx.x;
    const int w = t >> 5;         // 0..7
    const int row0 = blockIdx.x * 32;

    // ---- consts ----
    b1s[t] = b1[t];
    b2s[t] = b2[t];
    if (t < 64) { bqs[t] = bq[t]; whs[t] = Wh[t]; }

    // ---- fill helpers ----
    auto fillX = [&](int s, int buf) {   // 32x32 -> sX[buf]; 256 f4
        float* dst = sX + buf * 1152;
        const int r = t >> 3, c4 = t & 7;
        float4 v = *reinterpret_cast<const float4*>(X + (size_t)(row0 + r) * F_IN + s * 32 + c4 * 4);
        float4 o = make_float4(f2tf(v.x), f2tf(v.y), f2tf(v.z), f2tf(v.w));
        *reinterpret_cast<float4*>(dst + r * LDX + c4 * 4) = o;
    };
    auto fillW = [&](const float* __restrict__ W, int s, int buf) {  // 32x256; 2048 f4
        float* dst = sB + buf * 8320;
        #pragma unroll
        for (int h = 0; h < 2; ++h) {            // two halves, capped staging regs
            #pragma unroll
            for (int q = 0; q < 4; ++q) {
                const int idx = t + q * 256 + h * 1024;
                const int r = idx >> 6, c4 = idx & 63;
                float4 v = *reinterpret_cast<const float4*>(W + (size_t)(s * 32 + r) * H_DIM + c4 * 4);
                float4 o = make_float4(f2tf(v.x), f2tf(v.y), f2tf(v.z), f2tf(v.w));
                *reinterpret_cast<float4*>(dst + r * LDB + c4 * 4) = o;
            }
            asm volatile("" ::: "memory");       // compiler barrier: don't hoist half 2
        }
    };
    auto fillWq = [&](int s, int buf) {  // 32x64; 512 f4
        float* dst = sB + buf * 8320;
        #pragma unroll
        for (int q = 0; q < 2; ++q) {
            const int idx = t + q * 256;
            const int r = idx >> 4, c4 = idx & 15;
            float4 v = *reinterpret_cast<const float4*>(Wq + (size_t)(s * 32 + r) * W_DIM + c4 * 4);
            float4 o = make_float4(f2tf(v.x), f2tf(v.y), f2tf(v.z), f2tf(v.w));
            *reinterpret_cast<float4*>(dst + r * LDQ + c4 * 4) = o;
        }
    };

    // warp tile L1/L2: M-tiles {0,1} x N-tiles {2w, 2w+1}
    FragC acc[2][2];

    // ================= Layer 1: C1 = X @ W1  (K=512) =================
    #pragma unroll
    for (int i = 0; i < 2; ++i)
        #pragma unroll
        for (int j = 0; j < 2; ++j) wmma::fill_fragment(acc[i][j], 0.0f);

    fillX(0, 0); fillW(W1, 0, 0);
    __syncthreads();
    for (int s = 0; s < 16; ++s) {
        const int cb = s & 1;
        if (s < 15) { fillX(s + 1, cb ^ 1); fillW(W1, s + 1, cb ^ 1); }
        const float* ax = sX + cb * 1152;
        const float* bx = sB + cb * 8320;
        #pragma unroll
        for (int kk = 0; kk < 32; kk += 8) {
            FragA a[2];
            wmma::load_matrix_sync(a[0], ax + 0 * 16 * LDX + kk, LDX);
            wmma::load_matrix_sync(a[1], ax + 1 * 16 * LDX + kk, LDX);
            FragB b[2];
            wmma::load_matrix_sync(b[0], bx + kk * LDB + (2 * w + 0) * 16, LDB);
            wmma::load_matrix_sync(b[1], bx + kk * LDB + (2 * w + 1) * 16, LDB);
            #pragma unroll
            for (int i = 0; i < 2; ++i)
                #pragma unroll
                for (int j = 0; j < 2; ++j)
                    wmma::mma_sync(acc[i][j], a[i], b[j], acc[i][j]);
        }
        __syncthreads();
    }
    #pragma unroll
    for (int i = 0; i < 2; ++i)
        #pragma unroll
        for (int j = 0; j < 2; ++j)
            wmma::store_matrix_sync(sA + i * 16 * LDB + (2 * w + j) * 16, acc[i][j], LDB, wmma::mem_row_major);
    __syncthreads();
    #pragma unroll
    for (int i = 0; i < 32; ++i) {      // relu + b1, tf32-round in place
        const int idx = t + i * 256;
        const int r = idx >> 8, c = idx & 255;
        sA[r * LDB + c] = f2tf(fmaxf(sA[r * LDB + c] + b1s[c], 0.0f));
    }
    __syncthreads();

    // ================= Layer 2: C2 = act1 @ W2  (K=256), in place =================
    #pragma unroll
    for (int i = 0; i < 2; ++i)
        #pragma unroll
        for (int j = 0; j < 2; ++j) wmma::fill_fragment(acc[i][j], 0.0f);
    fillW(W2, 0, 0);
    __syncthreads();
    for (int s = 0; s < 8; ++s) {
        const int cb = s & 1;
        if (s < 7) fillW(W2, s + 1, cb ^ 1);
        const float* bx = sB + cb * 8320;
        #pragma unroll
        for (int kk = 0; kk < 32; kk += 8) {
            FragA a[2];
            wmma::load_matrix_sync(a[0], sA + 0 * 16 * LDB + s * 32 + kk, LDB);
            wmma::load_matrix_sync(a[1], sA + 1 * 16 * LDB + s * 32 + kk, LDB);
            FragB b[2];
            wmma::load_matrix_sync(b[0], bx + kk * LDB + (2 * w + 0) * 16, LDB);
            wmma::load_matrix_sync(b[1], bx + kk * LDB + (2 * w + 1) * 16, LDB);
            #pragma unroll
            for (int i = 0; i < 2; ++i)
                #pragma unroll
                for (int j = 0; j < 2; ++j)
                    wmma::mma_sync(acc[i][j], a[i], b[j], acc[i][j]);
        }
        __syncthreads();
    }
    #pragma unroll
    for (int i = 0; i < 2; ++i)
        #pragma unroll
        for (int j = 0; j < 2; ++j)
            wmma::store_matrix_sync(sA + i * 16 * LDB + (2 * w + j) * 16, acc[i][j], LDB, wmma::mem_row_major);
    __syncthreads();
    #pragma unroll
    for (int i = 0; i < 32; ++i) {      // relu + b2 in place
        const int idx = t + i * 256;
        const int r = idx >> 8, c = idx & 255;
        sA[r * LDB + c] = f2tf(fmaxf(sA[r * LDB + c] + b2s[c], 0.0f));
    }
    __syncthreads();

    // ================= Layer 3: C3 = act2 @ Wq  (K=256, N=64) =================
    FragC a3;
    wmma::fill_fragment(a3, 0.0f);
    const int mi3 = w >> 2;            // 0..1
    const int nj3 = w & 3;             // 0..3
    fillWq(0, 0);
    __syncthreads();
    for (int s = 0; s < 8; ++s) {
        const int cb = s & 1;
        if (s < 7) fillWq(s + 1, cb ^ 1);
        const float* bx = sB + cb * 8320;
        #pragma unroll
        for (int kk = 0; kk < 32; kk += 8) {
            FragA a;
            wmma::load_matrix_sync(a, sA + mi3 * 16 * LDB + s * 32 + kk, LDB);
            FragB b;
            wmma::load_matrix_sync(b, bx + kk * LDQ + nj3 * 16, LDQ);
            wmma::mma_sync(a3, a, b, a3);
        }
        __syncthreads();
    }
    // C3 overwrites A region (dead), stride LDQ
    wmma::store_matrix_sync(sA + mi3 * 16 * LDQ + nj3 * 16, a3, LDQ, wmma::mem_row_major);
    __syncthreads();

    // ---- Epilogue: sum_{r,c} tanh(C3 + bq[c]) * Wh[c]  -> per-CTA scalar ----
    float p = 0.0f;
    {
        const int r  = t & 31;
        const int c0 = (t >> 5) * 8;     // 8 groups x 8 cols
        #pragma unroll
        for (int c = 0; c < 8; ++c)
            p += tanhf(sA[r * LDQ + c0 + c] + bqs[c0 + c]) * whs[c0 + c];
    }
    #pragma unroll
    for (int off = 16; off > 0; off >>= 1)
        p += __shfl_down_sync(0xffffffffu, p, off);
    if ((t & 31) == 0) red[w] = p;
    __syncthreads();
    if (t == 0) {
        float s = 0.0f;
        #pragma unroll
        for (int i = 0; i < 8; ++i) s += red[i];
        g_part[blockIdx.x] = s;
        __threadfence();
        unsigned int v = atomicAdd(&g_cnt, 1u);
        flg[0] = (v == NBLK - 1) ? 1.0f : 0.0f;
    }
    __syncthreads();

    // ---- Last CTA: final reduction (fixed order -> deterministic) ----
    if (flg[0] != 0.0f) {
        __threadfence();
        float v = g_part[t];
        #pragma unroll
        for (int off = 16; off > 0; off >>= 1)
            v += __shfl_down_sync(0xffffffffu, v, off);
        if ((t & 31) == 0) red[w] = v;
        __syncthreads();
        if (t == 0) {
            float s = 0.0f;
            #pragma unroll
            for (int i = 0; i < 8; ++i) s += red[i];
            out[0] = s + bh[0];
            g_cnt = 0;                    // reset for next graph replay
        }
    }
}

extern "C" void kernel_launch(void* const* d_in, const int* in_sizes, int n_in,
                              void* d_out, int out_size)
{
    const float* X  = (const float*)d_in[0];
    const float* W1 = (const float*)d_in[1];
    const float* b1 = (const float*)d_in[2];
    const float* W2 = (const float*)d_in[3];
    const float* b2 = (const float*)d_in[4];
    const float* Wq = (const float*)d_in[5];
    const float* bq = (const float*)d_in[6];
    const float* Wh = (const float*)d_in[7];
    const float* bh = (const float*)d_in[8];

    cudaFuncSetAttribute(fused_wmma, cudaFuncAttributeMaxDynamicSharedMemorySize, SMEM_BYTES);
    fused_wmma<<<NBLK, THREADS, SMEM_BYTES>>>(X, W1, b1, W2, b2, Wq, bq, Wh, bh, (float*)d_out);
}

// round 10
// speedup vs baseline: 1.1752x; 1.1113x over previous
#include <cuda_runtime.h>
#include <mma.h>
#include <math.h>
#include <stdint.h>

using namespace nvcuda;

#define NBLK    128        // CTAs, 64 rows each
#define THREADS 256
#define F_IN    512
#define H_DIM   256
#define W_DIM   64

#define LDX 68             // X chunk  [64][64]
#define LDB 260            // W chunk  [64][256]; also act tile [64][256]
#define LDQ 68             // Wq chunk [64][64];  also C3 [64][64]

// float offsets inside dynamic smem
#define O_A    0                    // act 64x260 = 16640 (X 2-bufs alias [0,8704))
#define O_B    16640                // 2 x 64x260 = 33280 (W slabs; Wq uses 4352 each)
#define O_CON  49920                // b1(256) b2(256) bq(64) wh(64) red(8) flg(1)
#define SMEMF  50576
#define SMEM_BYTES (SMEMF * 4)      // 202304 B -> 1 CTA/SM

static __device__ float g_part[NBLK];
static __device__ unsigned int g_cnt = 0;
static __device__ float g_Wtf[212992];   // W1[131072] | W2[65536] | Wq[16384], tf32-rounded

__device__ __forceinline__ float f2tf(float f) {   // round-to-nearest tf32
    uint32_t r;
    asm("cvt.rna.tf32.f32 %0, %1;" : "=r"(r) : "f"(f));
    return __uint_as_float(r);
}
__device__ __forceinline__ void cpa16(uint32_t dst, const float* src) {
    asm volatile("cp.async.cg.shared.global [%0], [%1], 16;" :: "r"(dst), "l"(src));
}
#define CPA_COMMIT() asm volatile("cp.async.commit_group;" ::: "memory")
template<int N> __device__ __forceinline__ void cpa_wait() {
    asm volatile("cp.async.wait_group %0;" :: "n"(N) : "memory");
}

typedef wmma::fragment<wmma::matrix_a, 16, 16, 8, wmma::precision::tf32, wmma::row_major> FragA;
typedef wmma::fragment<wmma::matrix_b, 16, 16, 8, wmma::precision::tf32, wmma::row_major> FragB;
typedef wmma::fragment<wmma::accumulator, 16, 16, 8, float> FragC;

// Prologue: tf32-round all weights into g_Wtf (53248 float4s).
__global__ void conv_w(const float* __restrict__ W1, const float* __restrict__ W2,
                       const float* __restrict__ Wq)
{
    const int i = blockIdx.x * blockDim.x + threadIdx.x;
    if (i >= 53248) return;
    const float4* src;
    int off;
    if (i < 32768)      { src = (const float4*)W1; off = i; }
    else if (i < 49152) { src = (const float4*)W2; off = i - 32768; }
    else                { src = (const float4*)Wq; off = i - 49152; }
    float4 v = src[off];
    ((float4*)g_Wtf)[i] = make_float4(f2tf(v.x), f2tf(v.y), f2tf(v.z), f2tf(v.w));
}

__global__ void __launch_bounds__(THREADS, 1)
fused_wmma(const float* __restrict__ X,
           const float* __restrict__ b1, const float* __restrict__ b2,
           const float* __restrict__ bq, const float* __restrict__ Wh,
           const float* __restrict__ bh, float* __restrict__ out)
{
    extern __shared__ float sm[];
    float* sA  = sm + O_A;
    float* sB  = sm + O_B;
    float* b1s = sm + O_CON;
    float* b2s = b1s + 256;
    float* bqs = b2s + 256;
    float* whs = bqs + 64;
    float* red = whs + 64;
    float* flg = red + 8;
    const uint32_t sb32 = (uint32_t)__cvta_generic_to_shared(sm);

    const int t = threadIdx.x;
    const int w = t >> 5;         // 0..7
    const int row0 = blockIdx.x * 64;
    const int mg = w >> 2;        // 0..1 : M-tiles {2mg, 2mg+1}
    const int ng = w & 3;         // 0..3 : j-tiles {4ng..4ng+3}

    b1s[t] = b1[t];
    b2s[t] = b2[t];
    if (t < 64) { bqs[t] = bq[t]; whs[t] = Wh[t]; }

    const float* W1t = g_Wtf;
    const float* W2t = g_Wtf + 131072;
    const float* Wqt = g_Wtf + 196608;

    // X chunk 64x64 (tf32-rounded, manual) -> aliases act region
    auto fillX = [&](int s, int buf) {
        float* dst = sm + buf * 4352;
        #pragma unroll
        for (int q = 0; q < 4; ++q) {
            const int idx = t + q * 256;           // 0..1023 f4
            const int r = idx >> 4, c4 = idx & 15;
            float4 v = *reinterpret_cast<const float4*>(X + (size_t)(row0 + r) * F_IN + s * 64 + c4 * 4);
            *reinterpret_cast<float4*>(dst + r * LDX + c4 * 4) =
                make_float4(f2tf(v.x), f2tf(v.y), f2tf(v.z), f2tf(v.w));
        }
    };
    // W chunk 64x256 via cp.async (pre-rounded)
    auto fillW = [&](const float* __restrict__ Wt, int s, int buf) {
        const uint32_t dst = sb32 + (O_B + buf * 16640) * 4;
        #pragma unroll
        for (int q = 0; q < 16; ++q) {
            const int idx = t + q * 256;           // 0..4095 f4
            const int r = idx >> 6, c4 = idx & 63;
            cpa16(dst + (r * LDB + c4 * 4) * 4, Wt + (size_t)(s * 64 + r) * H_DIM + c4 * 4);
        }
    };
    // Wq chunk 64x64 via cp.async
    auto fillWq = [&](int s, int buf) {
        const uint32_t dst = sb32 + (O_B + buf * 16640) * 4;
        #pragma unroll
        for (int q = 0; q < 4; ++q) {
            const int idx = t + q * 256;           // 0..1023 f4
            const int r = idx >> 4, c4 = idx & 15;
            cpa16(dst + (r * LDQ + c4 * 4) * 4, Wqt + (size_t)(s * 64 + r) * W_DIM + c4 * 4);
        }
    };

    FragC acc[2][4];

    // ================= Layer 1: C1 = X @ W1  (K=512, 8 slabs of 64) =================
    #pragma unroll
    for (int i = 0; i < 2; ++i)
        #pragma unroll
        for (int j = 0; j < 4; ++j) wmma::fill_fragment(acc[i][j], 0.0f);

    fillX(0, 0); fillW(W1t, 0, 0); CPA_COMMIT();
    for (int s = 0; s < 8; ++s) {
        const int cb = s & 1;
        if (s < 7) { fillX(s + 1, cb ^ 1); fillW(W1t, s + 1, cb ^ 1); CPA_COMMIT(); cpa_wait<1>(); }
        else cpa_wait<0>();
        __syncthreads();
        const float* ax = sm + cb * 4352;
        const float* bx = sB + cb * 16640;
        #pragma unroll
        for (int kk = 0; kk < 64; kk += 8) {
            FragA a[2];
            wmma::load_matrix_sync(a[0], ax + (mg * 2 + 0) * 16 * LDX + kk, LDX);
            wmma::load_matrix_sync(a[1], ax + (mg * 2 + 1) * 16 * LDX + kk, LDX);
            #pragma unroll
            for (int j = 0; j < 4; ++j) {
                FragB b;
                wmma::load_matrix_sync(b, bx + kk * LDB + (ng * 4 + j) * 16, LDB);
                wmma::mma_sync(acc[0][j], a[0], b, acc[0][j]);
                wmma::mma_sync(acc[1][j], a[1], b, acc[1][j]);
            }
        }
        __syncthreads();
    }
    #pragma unroll
    for (int i = 0; i < 2; ++i)
        #pragma unroll
        for (int j = 0; j < 4; ++j)
            wmma::store_matrix_sync(sA + (mg * 2 + i) * 16 * LDB + (ng * 4 + j) * 16,
                                    acc[i][j], LDB, wmma::mem_row_major);
    __syncthreads();
    #pragma unroll
    for (int i = 0; i < 64; ++i) {      // relu + b1, tf32-round in place
        const int idx = t + i * 256;
        const int r = idx >> 8, c = idx & 255;
        sA[r * LDB + c] = f2tf(fmaxf(sA[r * LDB + c] + b1s[c], 0.0f));
    }
    __syncthreads();

    // ================= Layer 2: C2 = act1 @ W2  (K=256, 4 slabs), in place =================
    #pragma unroll
    for (int i = 0; i < 2; ++i)
        #pragma unroll
        for (int j = 0; j < 4; ++j) wmma::fill_fragment(acc[i][j], 0.0f);
    fillW(W2t, 0, 0); CPA_COMMIT();
    for (int s = 0; s < 4; ++s) {
        const int cb = s & 1;
        if (s < 3) { fillW(W2t, s + 1, cb ^ 1); CPA_COMMIT(); cpa_wait<1>(); }
        else cpa_wait<0>();
        __syncthreads();
        const float* bx = sB + cb * 16640;
        #pragma unroll
        for (int kk = 0; kk < 64; kk += 8) {
            FragA a[2];
            wmma::load_matrix_sync(a[0], sA + (mg * 2 + 0) * 16 * LDB + s * 64 + kk, LDB);
            wmma::load_matrix_sync(a[1], sA + (mg * 2 + 1) * 16 * LDB + s * 64 + kk, LDB);
            #pragma unroll
            for (int j = 0; j < 4; ++j) {
                FragB b;
                wmma::load_matrix_sync(b, bx + kk * LDB + (ng * 4 + j) * 16, LDB);
                wmma::mma_sync(acc[0][j], a[0], b, acc[0][j]);
                wmma::mma_sync(acc[1][j], a[1], b, acc[1][j]);
            }
        }
        __syncthreads();
    }
    #pragma unroll
    for (int i = 0; i < 2; ++i)
        #pragma unroll
        for (int j = 0; j < 4; ++j)
            wmma::store_matrix_sync(sA + (mg * 2 + i) * 16 * LDB + (ng * 4 + j) * 16,
                                    acc[i][j], LDB, wmma::mem_row_major);
    __syncthreads();
    #pragma unroll
    for (int i = 0; i < 64; ++i) {      // relu + b2 in place
        const int idx = t + i * 256;
        const int r = idx >> 8, c = idx & 255;
        sA[r * LDB + c] = f2tf(fmaxf(sA[r * LDB + c] + b2s[c], 0.0f));
    }
    __syncthreads();

    // ================= Layer 3: C3 = act2 @ Wq  (K=256, 4 slabs, N=64) =================
    FragC a3[2];
    wmma::fill_fragment(a3[0], 0.0f);
    wmma::fill_fragment(a3[1], 0.0f);
    const int mi3 = w >> 1;            // 0..3 : M-tile
    const int nh3 = w & 1;             // 0..1 : N-tiles {2nh3, 2nh3+1}
    fillWq(0, 0); CPA_COMMIT();
    for (int s = 0; s < 4; ++s) {
        const int cb = s & 1;
        if (s < 3) { fillWq(s + 1, cb ^ 1); CPA_COMMIT(); cpa_wait<1>(); }
        else cpa_wait<0>();
        __syncthreads();
        const float* bx = sB + cb * 16640;
        #pragma unroll
        for (int kk = 0; kk < 64; kk += 8) {
            FragA a;
            wmma::load_matrix_sync(a, sA + mi3 * 16 * LDB + s * 64 + kk, LDB);
            #pragma unroll
            for (int j = 0; j < 2; ++j) {
                FragB b;
                wmma::load_matrix_sync(b, bx + kk * LDQ + (nh3 * 2 + j) * 16, LDQ);
                wmma::mma_sync(a3[j], a, b, a3[j]);
            }
        }
        __syncthreads();
    }
    #pragma unroll
    for (int j = 0; j < 2; ++j)
        wmma::store_matrix_sync(sm + mi3 * 16 * LDQ + (nh3 * 2 + j) * 16,
                                a3[j], LDQ, wmma::mem_row_major);
    __syncthreads();

    // ---- Epilogue: sum_{r,c} tanh(C3 + bq[c]) * Wh[c]  -> per-CTA scalar ----
    float p = 0.0f;
    {
        const int r  = t & 63;
        const int c0 = (t >> 6) * 16;
        #pragma unroll
        for (int c = 0; c < 16; ++c)
            p += tanhf(sm[r * LDQ + c0 + c] + bqs[c0 + c]) * whs[c0 + c];
    }
    #pragma unroll
    for (int off = 16; off > 0; off >>= 1)
        p += __shfl_down_sync(0xffffffffu, p, off);
    if ((t & 31) == 0) red[w] = p;
    __syncthreads();
    if (t == 0) {
        float s = 0.0f;
        #pragma unroll
        for (int i = 0; i < 8; ++i) s += red[i];
        g_part[blockIdx.x] = s;
        __threadfence();
        unsigned int v = atomicAdd(&g_cnt, 1u);
        flg[0] = (v == NBLK - 1) ? 1.0f : 0.0f;
    }
    __syncthreads();

    // ---- Last CTA: final reduction (fixed order -> deterministic) ----
    if (flg[0] != 0.0f) {
        __threadfence();
        float v = 0.0f;
        if (t < 128) v = g_part[t];
        #pragma unroll
        for (int off = 16; off > 0; off >>= 1)
            v += __shfl_down_sync(0xffffffffu, v, off);
        if ((t & 31) == 0) red[w] = v;
        __syncthreads();
        if (t == 0) {
            out[0] = (red[0] + red[1]) + (red[2] + red[3]) + bh[0];
            g_cnt = 0;                    // reset for next graph replay
        }
    }
}

extern "C" void kernel_launch(void* const* d_in, const int* in_sizes, int n_in,
                              void* d_out, int out_size)
{
    const float* X  = (const float*)d_in[0];
    const float* W1 = (const float*)d_in[1];
    const float* b1 = (const float*)d_in[2];
    const float* W2 = (const float*)d_in[3];
    const float* b2 = (const float*)d_in[4];
    const float* Wq = (const float*)d_in[5];
    const float* bq = (const float*)d_in[6];
    const float* Wh = (const float*)d_in[7];
    const float* bh = (const float*)d_in[8];

    conv_w<<<208, 256>>>(W1, W2, Wq);
    cudaFuncSetAttribute(fused_wmma, cudaFuncAttributeMaxDynamicSharedMemorySize, SMEM_BYTES);
    fused_wmma<<<NBLK, THREADS, SMEM_BYTES>>>(X, b1, b2, bq, Wh, bh, (float*)d_out);
}